// round 16
// baseline (speedup 1.0000x reference)
#include <cuda_runtime.h>
#include <cuda_fp16.h>
#include <cstdint>

#define B_SZ   8192
#define D_IN   5000
#define H_SZ   512
#define T_SZ   16
#define K1PAD  5120
#define K3     8192

// ---------------- device scratch (static; no runtime allocation) ------------
__device__ __half gA1h[(size_t)B_SZ * K1PAD];
__device__ __half gA1l[(size_t)B_SZ * K1PAD];
__device__ __half gB1h[(size_t)H_SZ * K1PAD];
__device__ __half gB1l[(size_t)H_SZ * K1PAD];
__device__ __half gB3h[(size_t)H_SZ * K3];
__device__ __half gB3l[(size_t)H_SZ * K3];
__device__ __half gMh[(size_t)B_SZ * H_SZ];    // split planes of mlp_out
__device__ __half gMl[(size_t)B_SZ * H_SZ];
__device__ float g_mlp_out[(size_t)B_SZ * H_SZ];
__device__ float g_out1[(size_t)B_SZ * H_SZ];
__device__ float g_wtask[B_SZ * T_SZ];

// ---------------- helpers ----------------------------------------------------
__device__ __forceinline__ uint32_t smem_u32(const void* p) {
    uint32_t a;
    asm("{ .reg .u64 t; cvta.to.shared.u64 t, %1; cvt.u32.u64 %0, t; }"
        : "=r"(a) : "l"(p));
    return a;
}

__device__ __forceinline__ void cpa16(uint32_t d, const void* s) {
    asm volatile("cp.async.cg.shared.global [%0], [%1], 16;" :: "r"(d), "l"(s));
}
#define CP_COMMIT() asm volatile("cp.async.commit_group;" ::: "memory")
#define CP_WAIT1()  asm volatile("cp.async.wait_group 1;" ::: "memory")

__device__ __forceinline__ void ldsm4(uint32_t* r, uint32_t a) {
    asm volatile("ldmatrix.sync.aligned.m8n8.x4.shared.b16 {%0,%1,%2,%3}, [%4];"
                 : "=r"(r[0]), "=r"(r[1]), "=r"(r[2]), "=r"(r[3]) : "r"(a));
}

__device__ __forceinline__ void mma16816(float* c, const uint32_t* a,
                                         uint32_t b0, uint32_t b1) {
    asm volatile(
        "mma.sync.aligned.m16n8k16.row.col.f32.f16.f16.f32 "
        "{%0,%1,%2,%3}, {%4,%5,%6,%7}, {%8,%9}, {%0,%1,%2,%3};"
        : "+f"(c[0]), "+f"(c[1]), "+f"(c[2]), "+f"(c[3])
        : "r"(a[0]), "r"(a[1]), "r"(a[2]), "r"(a[3]), "r"(b0), "r"(b1));
}

// ---------------- split helpers ---------------------------------------------
__device__ __forceinline__ void split4h_store(__half* ph, __half* pl,
                                              size_t off, float4 v) {
    union { __half b[4]; uint2 u; } H, L;
    float x[4] = {v.x, v.y, v.z, v.w};
#pragma unroll
    for (int i = 0; i < 4; ++i) {
        __half h = __float2half_rn(x[i]);
        H.b[i] = h;
        L.b[i] = __float2half_rn(x[i] - __half2float(h));
    }
    *(uint2*)(ph + off) = H.u;
    *(uint2*)(pl + off) = L.u;
}

__device__ __forceinline__ void split2h_store(__half* ph, __half* pl,
                                              size_t off, float a, float b) {
    union { __half h[2]; uint32_t u; } H, L;
    __half ha = __float2half_rn(a);
    __half hb = __float2half_rn(b);
    H.h[0] = ha; H.h[1] = hb;
    L.h[0] = __float2half_rn(a - __half2float(ha));
    L.h[1] = __float2half_rn(b - __half2float(hb));
    *(uint32_t*)(ph + off) = H.u;
    *(uint32_t*)(pl + off) = L.u;
}

// ---------------- prep kernels ----------------------------------------------
__global__ void prep_A1(const float* __restrict__ x) {
    long idx = (long)blockIdx.x * 256 + threadIdx.x;
    int b  = (int)(idx / (K1PAD / 4));
    int c4 = (int)(idx % (K1PAD / 4));
    int c = c4 * 4;
    float4 v = make_float4(0.f, 0.f, 0.f, 0.f);
    if (c < D_IN) v = *(const float4*)(x + (size_t)b * D_IN + c);
    split4h_store(gA1h, gA1l, (size_t)b * K1PAD + c, v);
}

__global__ void prep_B1(const float* __restrict__ w) {
    long idx = (long)blockIdx.x * 256 + threadIdx.x;
    int n  = (int)(idx / (K1PAD / 4));
    int c4 = (int)(idx % (K1PAD / 4));
    int c = c4 * 4;
    float4 v = make_float4(0.f, 0.f, 0.f, 0.f);
    if (c < D_IN) v = *(const float4*)(w + (size_t)n * D_IN + c);
    split4h_store(gB1h, gB1l, (size_t)n * K1PAD + c, v);
}

// CM [K3=8192][H=512] -> gB3 [H=512][K3=8192] (transpose + split)
__global__ void prep_B3(const float* __restrict__ CM) {
    __shared__ float tile[32][33];
    int k0 = blockIdx.x * 32;
    int n0 = blockIdx.y * 32;
    int tx = threadIdx.x, ty = threadIdx.y;
#pragma unroll
    for (int j = 0; j < 32; j += 8)
        tile[ty + j][tx] = CM[(size_t)(k0 + ty + j) * H_SZ + n0 + tx];
    __syncthreads();
#pragma unroll
    for (int j = 0; j < 32; j += 8) {
        float v = tile[tx][ty + j];
        __half h = __float2half_rn(v);
        __half l = __float2half_rn(v - __half2float(h));
        size_t o = (size_t)(n0 + ty + j) * K3 + k0 + tx;
        gB3h[o] = h;
        gB3l[o] = l;
    }
}

// ---------------- HMMA GEMM --------------------------------------------------
// C[M=8192, N=512] = A @ B^T, fp16 split-2 (hi*hi + hi*lo + lo*hi), fp32 acc.
// CTA tile 64x64, BK=32, 3-stage pipeline, 8 warps (4M x 2N), warp tile 16x32.
// Smem: 64B rows, XOR swizzle (chunk ^= (row>>1)&3). Stage 16KB, 3 stages.
// MODE 0: A via cp.async from gA1 planes; C=g_mlp_out (+bias, + split planes).
// MODE 1: A fused on the fly = split(w[b,t] * (gMh+gMl)[b,h]) via STS;
//         B = gB3 planes via cp.async; C=g_out1.
#define BM 64
#define BN 64
#define BK 32
#define ROWB 64
#define PLANE_A (BM * ROWB)                 // 4096
#define PLANE_B (BN * ROWB)                 // 4096
#define STAGE (2 * PLANE_A + 2 * PLANE_B)   // 16384
#define OFF_AH 0
#define OFF_AL PLANE_A
#define OFF_BH (2 * PLANE_A)
#define OFF_BL (2 * PLANE_A + PLANE_B)
#define NSTAGE 3
#define SMEM_TOTAL (NSTAGE * STAGE)

__device__ __forceinline__ void sts16(uint32_t d, uint4 v) {
    asm volatile("st.shared.v4.b32 [%0], {%1,%2,%3,%4};"
                 :: "r"(d), "r"(v.x), "r"(v.y), "r"(v.z), "r"(v.w));
}

template <int MODE>
__device__ __forceinline__ void load_stage(uint32_t st,
                                           int m0, int n0, int K, int k0,
                                           int tid) {
    const int r = tid >> 2;             // 0..63
    const int c = tid & 3;              // 0..3 (16B chunk)
    const int sw = (r >> 1) & 3;
    const uint32_t o = (uint32_t)r * ROWB + (uint32_t)((c ^ sw) << 4);

    // B planes via cp.async (both modes)
    const __half* Bh = (MODE == 0) ? gB1h : gB3h;
    const __half* Bl = (MODE == 0) ? gB1l : gB3l;
    const size_t gb = (size_t)(n0 + r) * K + k0 + c * 8;
    cpa16(st + OFF_BH + o, Bh + gb);
    cpa16(st + OFF_BL + o, Bl + gb);

    if (MODE == 0) {
        const size_t ga = (size_t)(m0 + r) * K + k0 + c * 8;
        cpa16(st + OFF_AH + o, gA1h + ga);
        cpa16(st + OFF_AL + o, gA1l + ga);
    } else {
        // fused A' = split(w * mlp_out): chunk never straddles a task (512=8*64)
        const int t  = k0 >> 9;
        const int hb = (k0 & 511) + c * 8;
        const int row = m0 + r;
        const float w = g_wtask[row * T_SZ + t];
        union { uint4 u; __half h[8]; } MH, ML, OH, OL;
        MH.u = *(const uint4*)(gMh + (size_t)row * H_SZ + hb);
        ML.u = *(const uint4*)(gMl + (size_t)row * H_SZ + hb);
#pragma unroll
        for (int j = 0; j < 8; ++j) {
            float m = __half2float(MH.h[j]) + __half2float(ML.h[j]);
            float v = w * m;
            __half hh = __float2half_rn(v);
            OH.h[j] = hh;
            OL.h[j] = __float2half_rn(v - __half2float(hh));
        }
        sts16(st + OFF_AH + o, OH.u);
        sts16(st + OFF_AL + o, OL.u);
    }
}

template <int MODE>
__global__ void __launch_bounds__(256, 4)
gemm_hmma(const float* __restrict__ bias) {
    extern __shared__ char smem[];
    const uint32_t sb = smem_u32(smem);
    const int tid = threadIdx.x;
    const int wid = tid >> 5, lane = tid & 31;
    const int wm = wid >> 1;            // 0..3  (M, 16 rows each)
    const int wn = wid & 1;             // 0..1  (N, 32 cols each)

    const int K  = (MODE == 0) ? K1PAD : K3;
    const int nt = K / BK;
    float* __restrict__ C = (MODE == 0) ? g_mlp_out : g_out1;

    const int m0 = blockIdx.y * BM;
    const int n0 = blockIdx.x * BN;

    float acc[4][4];                    // [nb*2+half][4]
#pragma unroll
    for (int j = 0; j < 4; ++j)
#pragma unroll
        for (int q = 0; q < 4; ++q) acc[j][q] = 0.f;

    const int lrow = lane & 15;
    const int lk   = lane >> 4;

    uint32_t aro, asw;
    {
        int row = wm * 16 + lrow;
        aro = (uint32_t)row * ROWB;
        asw = (uint32_t)(((row >> 1) & 3) << 4);
    }
    uint32_t bro[2], bsw[2];
#pragma unroll
    for (int nb = 0; nb < 2; ++nb) {
        int row = wn * 32 + nb * 16 + lrow;
        bro[nb] = (uint32_t)row * ROWB;
        bsw[nb] = (uint32_t)(((row >> 1) & 3) << 4);
    }

    // prologue
    load_stage<MODE>(sb + 0 * STAGE, m0, n0, K, 0, tid);
    CP_COMMIT();
    load_stage<MODE>(sb + 1 * STAGE, m0, n0, K, BK, tid);
    CP_COMMIT();

    for (int i = 0; i < nt; ++i) {
        CP_WAIT1();
        __syncthreads();
        const uint32_t st = sb + (uint32_t)(i % NSTAGE) * STAGE;

        if (i + 2 < nt)
            load_stage<MODE>(sb + (uint32_t)((i + 2) % NSTAGE) * STAGE,
                             m0, n0, K, (i + 2) * BK, tid);
        CP_COMMIT();

#pragma unroll
        for (int ks = 0; ks < 2; ++ks) {
            const uint32_t cid = (uint32_t)((ks * 2 + lk) << 4);
            uint32_t aH[4], aL[4];
            {
                const uint32_t ro = aro + (cid ^ asw);
                ldsm4(aH, st + OFF_AH + ro);
                ldsm4(aL, st + OFF_AL + ro);
            }
#pragma unroll
            for (int nb = 0; nb < 2; ++nb) {
                uint32_t bH[4], bL[4];
                const uint32_t ro = bro[nb] + (cid ^ bsw[nb]);
                ldsm4(bH, st + OFF_BH + ro);
                ldsm4(bL, st + OFF_BL + ro);
                mma16816(acc[nb * 2],     aH, bH[0], bH[2]);
                mma16816(acc[nb * 2 + 1], aH, bH[1], bH[3]);
                mma16816(acc[nb * 2],     aH, bL[0], bL[2]);
                mma16816(acc[nb * 2 + 1], aH, bL[1], bL[3]);
                mma16816(acc[nb * 2],     aL, bH[0], bH[2]);
                mma16816(acc[nb * 2 + 1], aL, bH[1], bH[3]);
            }
        }
    }

    // epilogue
    const int gid = lane >> 2;
    const int tig = lane & 3;
#pragma unroll
    for (int nf = 0; nf < 4; ++nf) {
        const int nb = nf >> 1, half = nf & 1;
        const int row = m0 + wm * 16 + gid;
        const int col = n0 + wn * 32 + nb * 16 + half * 8 + 2 * tig;
        float2 v0 = make_float2(acc[nf][0], acc[nf][1]);
        float2 v1 = make_float2(acc[nf][2], acc[nf][3]);
        if (MODE == 0) {
            v0.x += bias[col]; v0.y += bias[col + 1];
            v1.x += bias[col]; v1.y += bias[col + 1];
            // split planes of mlp_out for the fused GEMM3 A-loader
            split2h_store(gMh, gMl, (size_t)row * H_SZ + col, v0.x, v0.y);
            split2h_store(gMh, gMl, (size_t)(row + 8) * H_SZ + col, v1.x, v1.y);
        }
        *(float2*)(C + (size_t)row * H_SZ + col)       = v0;
        *(float2*)(C + (size_t)(row + 8) * H_SZ + col) = v1;
    }
}

// ---------------- softmax over tasks (weights only) --------------------------
__global__ void attn_softmax_kernel(const float* __restrict__ attn) {
    __shared__ float row[H_SZ];
    __shared__ float s[T_SZ];
    const int b = blockIdx.x;
    const int tid = threadIdx.x;
    ((float2*)row)[tid] = ((const float2*)(g_mlp_out + (size_t)b * H_SZ))[tid];
    __syncthreads();
    const int warp = tid >> 5, lane = tid & 31;
#pragma unroll
    for (int tt = 0; tt < 2; ++tt) {
        const int t = warp * 2 + tt;
        float acc = 0.f;
#pragma unroll 4
        for (int h = lane; h < H_SZ; h += 32) acc += row[h] * attn[h * T_SZ + t];
#pragma unroll
        for (int o = 16; o; o >>= 1) acc += __shfl_xor_sync(0xffffffffu, acc, o);
        if (lane == 0) s[t] = acc;
    }
    __syncthreads();
    if (tid == 0) {
        float mx = s[0];
#pragma unroll
        for (int t = 1; t < T_SZ; ++t) mx = fmaxf(mx, s[t]);
        float e[T_SZ];
        float sum = 0.f;
#pragma unroll
        for (int t = 0; t < T_SZ; ++t) { e[t] = __expf(s[t] - mx); sum += e[t]; }
        float inv = 1.f / sum;
#pragma unroll
        for (int t = 0; t < T_SZ; ++t) g_wtask[b * T_SZ + t] = e[t] * inv;
    }
}

// ---------------- classifier + sigmoid --------------------------------------
__global__ void final_kernel(const float* __restrict__ cla_w,
                             const float* __restrict__ cla_b,
                             float* __restrict__ out) {
    const int gw = (blockIdx.x * blockDim.x + threadIdx.x) >> 5;
    const int lane = threadIdx.x & 31;
    if (gw >= B_SZ) return;
    const float4* rp = (const float4*)(g_out1 + (size_t)gw * H_SZ);
    const float4* wp = (const float4*)cla_w;
    float acc = 0.f;
#pragma unroll
    for (int i = lane; i < H_SZ / 4; i += 32) {
        float4 a = rp[i], w = wp[i];
        acc += a.x * w.x + a.y * w.y + a.z * w.z + a.w * w.w;
    }
#pragma unroll
    for (int o = 16; o; o >>= 1) acc += __shfl_xor_sync(0xffffffffu, acc, o);
    if (lane == 0) {
        float logit = acc + cla_b[0];
        out[gw] = 1.f / (1.f + __expf(-logit));
    }
}

// ---------------- launch -----------------------------------------------------
extern "C" void kernel_launch(void* const* d_in, const int* in_sizes, int n_in,
                              void* d_out, int out_size) {
    const float* data_input = (const float*)d_in[0];
    const float* mlp_w      = (const float*)d_in[1];
    const float* mlp_b      = (const float*)d_in[2];
    const float* CM         = (const float*)d_in[3];
    const float* attn       = (const float*)d_in[4];
    const float* cla_w      = (const float*)d_in[5];
    const float* cla_b      = (const float*)d_in[6];
    float* out = (float*)d_out;

    cudaFuncSetAttribute(gemm_hmma<0>, cudaFuncAttributeMaxDynamicSharedMemorySize,
                         SMEM_TOTAL);
    cudaFuncSetAttribute(gemm_hmma<1>, cudaFuncAttributeMaxDynamicSharedMemorySize,
                         SMEM_TOTAL);

    // input conversions
    prep_A1<<<(B_SZ * (K1PAD / 4)) / 256, 256>>>(data_input);
    prep_B1<<<(H_SZ * (K1PAD / 4)) / 256, 256>>>(mlp_w);
    prep_B3<<<dim3(K3 / 32, H_SZ / 32), dim3(32, 8)>>>(CM);

    // GEMM1: mlp_out = data @ mlp_w^T + b  (also emits split planes gMh/gMl)
    gemm_hmma<0><<<dim3(H_SZ / BN, B_SZ / BM), 256, SMEM_TOTAL>>>(mlp_b);

    // softmax task weights (0.5 MB output; A' no longer materialized)
    attn_softmax_kernel<<<B_SZ, 256>>>(attn);

    // GEMM3: out1 = A'(w, mlp_out) @ CM^T with fused A-loader
    gemm_hmma<1><<<dim3(H_SZ / BN, B_SZ / BM), 256, SMEM_TOTAL>>>(nullptr);

    // classifier + sigmoid
    final_kernel<<<(B_SZ * 32) / 256, 256>>>(cla_w, cla_b, out);
}

// round 17
// speedup vs baseline: 1.1555x; 1.1555x over previous
#include <cuda_runtime.h>
#include <cuda_fp16.h>
#include <cstdint>

#define B_SZ   8192
#define D_IN   5000
#define H_SZ   512
#define T_SZ   16
#define K1PAD  5024          // 32*157, smallest BK-multiple >= 5000
#define K3     8192

// ---------------- device scratch (static; no runtime allocation) ------------
__device__ __half gA1h[(size_t)B_SZ * K1PAD];
__device__ __half gA1l[(size_t)B_SZ * K1PAD];
__device__ __half gB1h[(size_t)H_SZ * K1PAD];
__device__ __half gB1l[(size_t)H_SZ * K1PAD];
__device__ __half gA3h[(size_t)B_SZ * K3];
__device__ __half gA3l[(size_t)B_SZ * K3];
__device__ __half gB3h[(size_t)H_SZ * K3];
__device__ __half gB3l[(size_t)H_SZ * K3];
__device__ float g_mlp_out[(size_t)B_SZ * H_SZ];
__device__ float g_out1[(size_t)B_SZ * H_SZ];

// ---------------- helpers ----------------------------------------------------
__device__ __forceinline__ uint32_t smem_u32(const void* p) {
    uint32_t a;
    asm("{ .reg .u64 t; cvta.to.shared.u64 t, %1; cvt.u32.u64 %0, t; }"
        : "=r"(a) : "l"(p));
    return a;
}

__device__ __forceinline__ void cpa16(uint32_t d, const void* s) {
    asm volatile("cp.async.cg.shared.global [%0], [%1], 16;" :: "r"(d), "l"(s));
}
#define CP_COMMIT() asm volatile("cp.async.commit_group;" ::: "memory")
#define CP_WAIT1()  asm volatile("cp.async.wait_group 1;" ::: "memory")

__device__ __forceinline__ void ldsm4(uint32_t* r, uint32_t a) {
    asm volatile("ldmatrix.sync.aligned.m8n8.x4.shared.b16 {%0,%1,%2,%3}, [%4];"
                 : "=r"(r[0]), "=r"(r[1]), "=r"(r[2]), "=r"(r[3]) : "r"(a));
}

__device__ __forceinline__ void mma16816(float* c, const uint32_t* a,
                                         uint32_t b0, uint32_t b1) {
    asm volatile(
        "mma.sync.aligned.m16n8k16.row.col.f32.f16.f16.f32 "
        "{%0,%1,%2,%3}, {%4,%5,%6,%7}, {%8,%9}, {%0,%1,%2,%3};"
        : "+f"(c[0]), "+f"(c[1]), "+f"(c[2]), "+f"(c[3])
        : "r"(a[0]), "r"(a[1]), "r"(a[2]), "r"(a[3]), "r"(b0), "r"(b1));
}

// ---------------- split helpers ---------------------------------------------
__device__ __forceinline__ void split4h_store(__half* ph, __half* pl,
                                              size_t off, float4 v) {
    union { __half b[4]; uint2 u; } H, L;
    float x[4] = {v.x, v.y, v.z, v.w};
#pragma unroll
    for (int i = 0; i < 4; ++i) {
        __half h = __float2half_rn(x[i]);
        H.b[i] = h;
        L.b[i] = __float2half_rn(x[i] - __half2float(h));
    }
    *(uint2*)(ph + off) = H.u;
    *(uint2*)(pl + off) = L.u;
}

// ---------------- prep: A1 + B1 merged (same structure) ----------------------
#define K1C4 (K1PAD / 4)     // 1256 float4-chunks per row
__global__ void prep_AB1(const float* __restrict__ x,
                         const float* __restrict__ w) {
    long idx = (long)blockIdx.x * 256 + threadIdx.x;
    const long nA = (long)B_SZ * K1C4;
    if (idx < nA) {
        int b  = (int)(idx / K1C4);
        int c  = (int)(idx % K1C4) * 4;
        float4 v = make_float4(0.f, 0.f, 0.f, 0.f);
        if (c < D_IN) v = *(const float4*)(x + (size_t)b * D_IN + c);
        split4h_store(gA1h, gA1l, (size_t)b * K1PAD + c, v);
    } else {
        idx -= nA;
        int n  = (int)(idx / K1C4);
        int c  = (int)(idx % K1C4) * 4;
        float4 v = make_float4(0.f, 0.f, 0.f, 0.f);
        if (c < D_IN) v = *(const float4*)(w + (size_t)n * D_IN + c);
        split4h_store(gB1h, gB1l, (size_t)n * K1PAD + c, v);
    }
}

// CM [K3=8192][H=512] -> gB3 [H=512][K3=8192] (transpose + split)
__global__ void prep_B3(const float* __restrict__ CM) {
    __shared__ float tile[32][33];
    int k0 = blockIdx.x * 32;
    int n0 = blockIdx.y * 32;
    int tx = threadIdx.x, ty = threadIdx.y;
#pragma unroll
    for (int j = 0; j < 32; j += 8)
        tile[ty + j][tx] = CM[(size_t)(k0 + ty + j) * H_SZ + n0 + tx];
    __syncthreads();
#pragma unroll
    for (int j = 0; j < 32; j += 8) {
        float v = tile[tx][ty + j];
        __half h = __float2half_rn(v);
        __half l = __float2half_rn(v - __half2float(h));
        size_t o = (size_t)(n0 + ty + j) * K3 + k0 + tx;
        gB3h[o] = h;
        gB3l[o] = l;
    }
}

// ---------------- HMMA GEMM --------------------------------------------------
// C[M=8192, N=512] = A @ B^T, fp16 split-2 (hi*hi + hi*lo + lo*hi), fp32 acc.
// CTA tile 64x64, BK=32, 3-stage cp.async pipeline, 8 warps (4M x 2N),
// warp tile 16x32. Smem: 64B rows, XOR swizzle (chunk ^= (row>>1)&3).
// Stage 16KB, 3 stages = 48KB; 64 regs -> 4 CTAs/SM (resource-pinned).
#define BM 64
#define BN 64
#define BK 32
#define ROWB 64
#define PLANE_A (BM * ROWB)                 // 4096
#define PLANE_B (BN * ROWB)                 // 4096
#define STAGE (2 * PLANE_A + 2 * PLANE_B)   // 16384
#define OFF_AH 0
#define OFF_AL PLANE_A
#define OFF_BH (2 * PLANE_A)
#define OFF_BL (2 * PLANE_A + PLANE_B)
#define NSTAGE 3
#define SMEM_TOTAL (NSTAGE * STAGE)

__device__ __forceinline__ void load_stage(uint32_t st,
                                           const __half* __restrict__ Ah,
                                           const __half* __restrict__ Al,
                                           const __half* __restrict__ Bh,
                                           const __half* __restrict__ Bl,
                                           int m0, int n0, int K, int k0,
                                           int tid) {
    const int r = tid >> 2;
    const int c = tid & 3;
    const int sw = (r >> 1) & 3;
    const uint32_t o = (uint32_t)r * ROWB + (uint32_t)((c ^ sw) << 4);
    const size_t ga = (size_t)(m0 + r) * K + k0 + c * 8;
    const size_t gb = (size_t)(n0 + r) * K + k0 + c * 8;
    cpa16(st + OFF_AH + o, Ah + ga);
    cpa16(st + OFF_AL + o, Al + ga);
    cpa16(st + OFF_BH + o, Bh + gb);
    cpa16(st + OFF_BL + o, Bl + gb);
}

template <int MODE>
__global__ void __launch_bounds__(256, 4)
gemm_hmma(const float* __restrict__ bias) {
    extern __shared__ char smem[];
    const uint32_t sb = smem_u32(smem);
    const int tid = threadIdx.x;
    const int wid = tid >> 5, lane = tid & 31;
    const int wm = wid >> 1;            // 0..3  (M, 16 rows each)
    const int wn = wid & 1;             // 0..1  (N, 32 cols each)

    const int K  = (MODE == 0) ? K1PAD : K3;
    const int nt = K / BK;
    const __half* Ah = (MODE == 0) ? gA1h : gA3h;
    const __half* Al = (MODE == 0) ? gA1l : gA3l;
    const __half* Bh = (MODE == 0) ? gB1h : gB3h;
    const __half* Bl = (MODE == 0) ? gB1l : gB3l;
    float* __restrict__ C = (MODE == 0) ? g_mlp_out : g_out1;

    const int m0 = blockIdx.y * BM;
    const int n0 = blockIdx.x * BN;

    float acc[4][4];                    // [nb*2+half][4]
#pragma unroll
    for (int j = 0; j < 4; ++j)
#pragma unroll
        for (int q = 0; q < 4; ++q) acc[j][q] = 0.f;

    const int lrow = lane & 15;
    const int lk   = lane >> 4;

    uint32_t aro, asw;
    {
        int row = wm * 16 + lrow;
        aro = (uint32_t)row * ROWB;
        asw = (uint32_t)(((row >> 1) & 3) << 4);
    }
    uint32_t bro[2], bsw[2];
#pragma unroll
    for (int nb = 0; nb < 2; ++nb) {
        int row = wn * 32 + nb * 16 + lrow;
        bro[nb] = (uint32_t)row * ROWB;
        bsw[nb] = (uint32_t)(((row >> 1) & 3) << 4);
    }

    // prologue
    load_stage(sb + 0 * STAGE, Ah, Al, Bh, Bl, m0, n0, K, 0, tid);
    CP_COMMIT();
    load_stage(sb + 1 * STAGE, Ah, Al, Bh, Bl, m0, n0, K, BK, tid);
    CP_COMMIT();

    for (int i = 0; i < nt; ++i) {
        CP_WAIT1();
        __syncthreads();
        const uint32_t st = sb + (uint32_t)(i % NSTAGE) * STAGE;

        if (i + 2 < nt)
            load_stage(sb + (uint32_t)((i + 2) % NSTAGE) * STAGE,
                       Ah, Al, Bh, Bl, m0, n0, K, (i + 2) * BK, tid);
        CP_COMMIT();

#pragma unroll
        for (int ks = 0; ks < 2; ++ks) {
            const uint32_t cid = (uint32_t)((ks * 2 + lk) << 4);
            uint32_t aH[4], aL[4];
            {
                const uint32_t ro = aro + (cid ^ asw);
                ldsm4(aH, st + OFF_AH + ro);
                ldsm4(aL, st + OFF_AL + ro);
            }
#pragma unroll
            for (int nb = 0; nb < 2; ++nb) {
                uint32_t bH[4], bL[4];
                const uint32_t ro = bro[nb] + (cid ^ bsw[nb]);
                ldsm4(bH, st + OFF_BH + ro);
                ldsm4(bL, st + OFF_BL + ro);
                mma16816(acc[nb * 2],     aH, bH[0], bH[2]);
                mma16816(acc[nb * 2 + 1], aH, bH[1], bH[3]);
                mma16816(acc[nb * 2],     aH, bL[0], bL[2]);
                mma16816(acc[nb * 2 + 1], aH, bL[1], bL[3]);
                mma16816(acc[nb * 2],     aL, bH[0], bH[2]);
                mma16816(acc[nb * 2 + 1], aL, bH[1], bH[3]);
            }
        }
    }

    // epilogue
    const int gid = lane >> 2;
    const int tig = lane & 3;
#pragma unroll
    for (int nf = 0; nf < 4; ++nf) {
        const int nb = nf >> 1, half = nf & 1;
        const int row = m0 + wm * 16 + gid;
        const int col = n0 + wn * 32 + nb * 16 + half * 8 + 2 * tig;
        float2 v0 = make_float2(acc[nf][0], acc[nf][1]);
        float2 v1 = make_float2(acc[nf][2], acc[nf][3]);
        if (MODE == 0) {
            v0.x += bias[col]; v0.y += bias[col + 1];
            v1.x += bias[col]; v1.y += bias[col + 1];
        }
        *(float2*)(C + (size_t)row * H_SZ + col)       = v0;
        *(float2*)(C + (size_t)(row + 8) * H_SZ + col) = v1;
    }
}

// ---------------- softmax over tasks + vectorized A3 build -------------------
// w[b,t] = softmax_t(mlp_out[b,:] @ attn[:,t]); then
// gA3{h,l}[b, t*512 + h] = split(w[b,t] * mlp_out[b,h]) with 16B stores.
__global__ void attn_softmax_kernel(const float* __restrict__ attn) {
    __shared__ float row[H_SZ];
    __shared__ float s[T_SZ];
    __shared__ float wsh[T_SZ];
    const int b = blockIdx.x;
    const int tid = threadIdx.x;
    ((float2*)row)[tid] = ((const float2*)(g_mlp_out + (size_t)b * H_SZ))[tid];
    __syncthreads();
    const int warp = tid >> 5, lane = tid & 31;
#pragma unroll
    for (int tt = 0; tt < 2; ++tt) {
        const int t = warp * 2 + tt;
        float acc = 0.f;
#pragma unroll 4
        for (int h = lane; h < H_SZ; h += 32) acc += row[h] * attn[h * T_SZ + t];
#pragma unroll
        for (int o = 16; o; o >>= 1) acc += __shfl_xor_sync(0xffffffffu, acc, o);
        if (lane == 0) s[t] = acc;
    }
    __syncthreads();
    if (tid == 0) {
        float mx = s[0];
#pragma unroll
        for (int t = 1; t < T_SZ; ++t) mx = fmaxf(mx, s[t]);
        float e[T_SZ];
        float sum = 0.f;
#pragma unroll
        for (int t = 0; t < T_SZ; ++t) { e[t] = __expf(s[t] - mx); sum += e[t]; }
        float inv = 1.f / sum;
#pragma unroll
        for (int t = 0; t < T_SZ; ++t) wsh[t] = e[t] * inv;
    }
    __syncthreads();
    // A' build: item = (t, 8-wide h-chunk); 16*64 = 1024 items, 4 per thread.
    // 16B coalesced stores per plane.
#pragma unroll
    for (int q = 0; q < 4; ++q) {
        const int it = tid + q * 256;
        const int t  = it >> 6;
        const int hc = (it & 63) * 8;
        const float wv = wsh[t];
        union { uint4 u; __half h[8]; } OH, OL;
#pragma unroll
        for (int j = 0; j < 8; ++j) {
            float v = wv * row[hc + j];
            __half hh = __float2half_rn(v);
            OH.h[j] = hh;
            OL.h[j] = __float2half_rn(v - __half2float(hh));
        }
        const size_t o = (size_t)b * K3 + t * H_SZ + hc;
        *(uint4*)(gA3h + o) = OH.u;
        *(uint4*)(gA3l + o) = OL.u;
    }
}

// ---------------- classifier + sigmoid --------------------------------------
__global__ void final_kernel(const float* __restrict__ cla_w,
                             const float* __restrict__ cla_b,
                             float* __restrict__ out) {
    const int gw = (blockIdx.x * blockDim.x + threadIdx.x) >> 5;
    const int lane = threadIdx.x & 31;
    if (gw >= B_SZ) return;
    const float4* rp = (const float4*)(g_out1 + (size_t)gw * H_SZ);
    const float4* wp = (const float4*)cla_w;
    float acc = 0.f;
#pragma unroll
    for (int i = lane; i < H_SZ / 4; i += 32) {
        float4 a = rp[i], w = wp[i];
        acc += a.x * w.x + a.y * w.y + a.z * w.z + a.w * w.w;
    }
#pragma unroll
    for (int o = 16; o; o >>= 1) acc += __shfl_xor_sync(0xffffffffu, acc, o);
    if (lane == 0) {
        float logit = acc + cla_b[0];
        out[gw] = 1.f / (1.f + __expf(-logit));
    }
}

// ---------------- launch -----------------------------------------------------
extern "C" void kernel_launch(void* const* d_in, const int* in_sizes, int n_in,
                              void* d_out, int out_size) {
    const float* data_input = (const float*)d_in[0];
    const float* mlp_w      = (const float*)d_in[1];
    const float* mlp_b      = (const float*)d_in[2];
    const float* CM         = (const float*)d_in[3];
    const float* attn       = (const float*)d_in[4];
    const float* cla_w      = (const float*)d_in[5];
    const float* cla_b      = (const float*)d_in[6];
    float* out = (float*)d_out;

    cudaFuncSetAttribute(gemm_hmma<0>, cudaFuncAttributeMaxDynamicSharedMemorySize,
                         SMEM_TOTAL);
    cudaFuncSetAttribute(gemm_hmma<1>, cudaFuncAttributeMaxDynamicSharedMemorySize,
                         SMEM_TOTAL);

    // input conversions (A1 + B1 merged; B3 separate)
    {
        long items = (long)(B_SZ + H_SZ) * K1C4;        // 8704 * 1256
        prep_AB1<<<(int)(items / 256), 256>>>(data_input, mlp_w);
    }
    prep_B3<<<dim3(K3 / 32, H_SZ / 32), dim3(32, 8)>>>(CM);

    // GEMM1: mlp_out = data @ mlp_w^T + b   (grid 8 x 128 = 1024 CTAs)
    gemm_hmma<0><<<dim3(H_SZ / BN, B_SZ / BM), 256, SMEM_TOTAL>>>(mlp_b);

    // softmax task weights + vectorized A' split build
    attn_softmax_kernel<<<B_SZ, 256>>>(attn);

    // GEMM3: out1 = A' @ CM^T
    gemm_hmma<1><<<dim3(H_SZ / BN, B_SZ / BM), 256, SMEM_TOTAL>>>(nullptr);

    // classifier + sigmoid
    final_kernel<<<(B_SZ * 32) / 256, 256>>>(cla_w, cla_b, out);
}